// round 1
// baseline (speedup 1.0000x reference)
#include <cuda_runtime.h>
#include <cstdint>

// Problem constants
#define CC   128
#define HH   64
#define WW   64
#define BB   8
#define EE   8
#define NG   4     // gates
#define HWPIX 4096 // 64*64
#define IMG  524288 // 128*64*64
#define YSZ  4194304 // 8*128*64*64

// device scratch (no allocs allowed)
__device__ float g_x0[BB * CC];          // batch-mean features
__device__ float g_w[NG * BB * EE];      // dense gate weights (0 => skip)

// ---------------------------------------------------------------------------
// Kernel 1: x0[b][c] = mean over H,W
// ---------------------------------------------------------------------------
__global__ void mean_kernel(const float* __restrict__ x) {
    int bc = blockIdx.x;                 // 0..1023 = b*128+c
    const float* p = x + (size_t)bc * HWPIX;
    float s = 0.f;
    for (int i = threadIdx.x; i < HWPIX; i += 256) s += p[i];
    for (int o = 16; o; o >>= 1) s += __shfl_xor_sync(0xffffffffu, s, o);
    __shared__ float sm[8];
    if ((threadIdx.x & 31) == 0) sm[threadIdx.x >> 5] = s;
    __syncthreads();
    if (threadIdx.x < 8) {
        float v = sm[threadIdx.x];
        for (int o = 4; o; o >>= 1) v += __shfl_xor_sync(0xffu, v, o);
        if (threadIdx.x == 0) g_x0[bc] = v * (1.0f / 4096.0f);
    }
}

// ---------------------------------------------------------------------------
// Kernel 2: gates. 1 block, 32 threads; lane = (g,b). Writes g_w and loss.
// ---------------------------------------------------------------------------
__global__ void gate_kernel(const float* __restrict__ g1, const float* __restrict__ g2,
                            const float* __restrict__ g3, const float* __restrict__ g4,
                            float* __restrict__ loss_out) {
    int lane = threadIdx.x;
    int g = lane >> 3, b = lane & 7;
    const float* G = (g == 0) ? g1 : (g == 1) ? g2 : (g == 2) ? g3 : g4;
    const float* x0 = &g_x0[b * CC];

    float lg[8];
#pragma unroll
    for (int e = 0; e < 8; e++) lg[e] = 0.f;
    for (int c = 0; c < CC; c++) {
        float xv = x0[c];
#pragma unroll
        for (int e = 0; e < 8; e++) lg[e] += xv * G[c * 8 + e];
    }
    // softmax over experts
    float m = lg[0];
#pragma unroll
    for (int e = 1; e < 8; e++) m = fmaxf(m, lg[e]);
    float p[8], sum = 0.f;
#pragma unroll
    for (int e = 0; e < 8; e++) { p[e] = expf(lg[e] - m); sum += p[e]; }
    float inv = 1.f / sum;
#pragma unroll
    for (int e = 0; e < 8; e++) p[e] *= inv;

    // top-2 (ties: lowest index first, matches lax.top_k)
    int i1 = 0;
#pragma unroll
    for (int e = 1; e < 8; e++) if (p[e] > p[i1]) i1 = e;
    int i2 = (i1 == 0) ? 1 : 0;
#pragma unroll
    for (int e = 0; e < 8; e++) { if (e == i1 || e == i2) continue; if (p[e] > p[i2]) i2 = e; }
    // softmax over the two selected probabilities
    float m2 = fmaxf(p[i1], p[i2]);
    float e1 = expf(p[i1] - m2), e2 = expf(p[i2] - m2);
    float winv = 1.f / (e1 + e2);
    float w1 = e1 * winv, w2 = e2 * winv;

    float* wrow = &g_w[(g * 8 + b) * 8];
#pragma unroll
    for (int e = 0; e < 8; e++) wrow[e] = 0.f;
    wrow[i1] = w1;
    wrow[i2] = w2;

    // usage = sum over batch of p (8-lane groups share g)
    float u[8];
#pragma unroll
    for (int e = 0; e < 8; e++) {
        u[e] = p[e];
        for (int o = 1; o < 8; o <<= 1) u[e] += __shfl_xor_sync(0xffffffffu, u[e], o);
    }
    __shared__ float sl[4];
    if (b == 0) {
        float mu = 0.f;
#pragma unroll
        for (int e = 0; e < 8; e++) mu += u[e];
        mu *= (1.0f / 8.0f);
        float var = 0.f;
#pragma unroll
        for (int e = 0; e < 8; e++) { float d = u[e] - mu; var += d * d; }
        var *= (1.0f / 7.0f);
        sl[g] = var / (mu * mu + 1e-10f);
    }
    __syncwarp();
    if (lane == 0) loss_out[0] = sl[0] + sl[1] + sl[2] + sl[3];
}

// ---------------------------------------------------------------------------
// Main fused expert kernel.
// Grid: 1024 blocks = b(8) x row(64) x seg(2). 128 threads.
// Block computes, for its 1x32 pixel strip, for every selected expert:
//   u = conv3x3(x) + b_caps; u = squash(u); v = W_proj @ u + b_proj;
//   y[g] += w[g,b,e] * v    (y held in smem, written once at the end)
// ---------------------------------------------------------------------------

// smem layout (floats)
#define OFF_SX    0          // x tile: [ci][3 rows][34 cols] = 128*102
#define OFF_SY    13056      // y acc : [g][co][33] = 4*4224
#define OFF_SW0   29952      // W_caps chunk buf0: [co][73]  (73 = 72 + pad)
#define OFF_SW1   39296      // buf1
#define OFF_SWP   29952      // W_proj (phase 2, overlaps SW bufs): [co][129]
#define OFF_SU    48640      // u tile: [ci][33]
#define OFF_SWG   52864      // gate weights w[4][8]
#define OFF_SPART 52896      // squash partials [4][32]
#define OFF_SSC   53024      // squash scales [32]
#define SMEM_FLOATS 53056
#define SMEM_BYTES  (SMEM_FLOATS * 4)

__device__ __forceinline__ uint32_t smem_u32(const void* p) {
    return (uint32_t)__cvta_generic_to_shared(p);
}
__device__ __forceinline__ void cp4(uint32_t dst, const float* src) {
    asm volatile("cp.async.ca.shared.global [%0], [%1], 4;" :: "r"(dst), "l"(src));
}

__global__ void __launch_bounds__(128, 1)
moe_main(const float* __restrict__ x,
         const float* __restrict__ Wc_all, const float* __restrict__ bc_all,
         const float* __restrict__ Wp_all, const float* __restrict__ bp_all,
         float* __restrict__ out) {
    extern __shared__ float sm[];
    float* sx  = sm + OFF_SX;
    float* sy  = sm + OFF_SY;
    float* sw0 = sm + OFF_SW0;
    float* swp = sm + OFF_SWP;
    float* su  = sm + OFF_SU;
    float* swg = sm + OFF_SWG;
    float* spart = sm + OFF_SPART;
    float* ssc = sm + OFF_SSC;

    const int tid = threadIdx.x;
    const int b   = blockIdx.x >> 7;
    const int t   = blockIdx.x & 127;
    const int row = t >> 1;
    const int seg = t & 1;
    const int cg = tid >> 3, pg = tid & 7;
    const int co_base = cg * 8, px_base = pg * 4;

    // gate weights for this batch
    if (tid < 32) {
        int g = tid >> 3, e = tid & 7;
        swg[tid] = g_w[(g * 8 + b) * 8 + e];
    }
    // zero y accumulators
    for (int i = tid; i < NG * 4224; i += 128) sy[i] = 0.f;
    // load x strip with 1-halo: [ci][rl 0..2][col 0..33]
    {
        const float* xb = x + (size_t)b * IMG;
        for (int i = tid; i < 13056; i += 128) {
            int ci  = i / 102;
            int rem = i - ci * 102;
            int rl  = rem / 34;
            int col = rem - rl * 34;
            int gr = row - 1 + rl;
            int gc = seg * 32 - 1 + col;
            float v = 0.f;
            if ((unsigned)gr < 64u && (unsigned)gc < 64u)
                v = xb[ci * HWPIX + gr * 64 + gc];
            sx[i] = v;
        }
    }
    __syncthreads();

    float acc[8][4];

    for (int e = 0; e < EE; ++e) {
        float wg0 = swg[e], wg1 = swg[8 + e], wg2 = swg[16 + e], wg3 = swg[24 + e];
        if (wg0 == 0.f && wg1 == 0.f && wg2 == 0.f && wg3 == 0.f) continue;  // skip unselected

        const float* Wc = Wc_all + (size_t)e * (CC * 1152);
        // ---- GEMM1: u[128co x 32px], K=1152, streamed in 16 chunks of 8 ci ----
        // prologue: chunk 0  (thread tid owns co=tid; 72 contiguous floats)
        {
            uint32_t dst = smem_u32(sw0 + tid * 73);
            const float* src = Wc + (size_t)tid * 1152;
#pragma unroll 8
            for (int r = 0; r < 72; ++r) cp4(dst + r * 4, src + r);
            asm volatile("cp.async.commit_group;");
        }
#pragma unroll
        for (int j = 0; j < 8; j++)
#pragma unroll
            for (int i = 0; i < 4; i++) acc[j][i] = 0.f;

        for (int cc = 0; cc < 16; ++cc) {
            if (cc < 15) {
                uint32_t dst = smem_u32(sw0 + ((cc + 1) & 1) * 9344 + tid * 73);
                const float* src = Wc + (size_t)tid * 1152 + (cc + 1) * 72;
#pragma unroll 8
                for (int r = 0; r < 72; ++r) cp4(dst + r * 4, src + r);
                asm volatile("cp.async.commit_group;");
                asm volatile("cp.async.wait_group 1;");
            } else {
                asm volatile("cp.async.wait_group 0;");
            }
            __syncthreads();
            const float* wb = sw0 + (cc & 1) * 9344 + co_base * 73;
            const float* xc = sx + cc * 8 * 102 + px_base;
#pragma unroll 2
            for (int cil = 0; cil < 8; ++cil) {
                const float* wci = wb + cil * 9;
                const float* xci = xc + cil * 102;
#pragma unroll
                for (int kidx = 0; kidx < 9; ++kidx) {
                    const int ky = kidx / 3, kx = kidx - 3 * (kidx / 3);
                    float a[8], bv[4];
#pragma unroll
                    for (int j = 0; j < 8; j++) a[j] = wci[j * 73 + kidx];
#pragma unroll
                    for (int i = 0; i < 4; i++) bv[i] = xci[ky * 34 + kx + i];
#pragma unroll
                    for (int j = 0; j < 8; j++)
#pragma unroll
                        for (int i = 0; i < 4; i++)
                            acc[j][i] = fmaf(a[j], bv[i], acc[j][i]);
                }
            }
            __syncthreads();
        }

        // bias + store u to smem
#pragma unroll
        for (int j = 0; j < 8; j++) {
            float bj = __ldg(&bc_all[e * CC + co_base + j]);
#pragma unroll
            for (int i = 0; i < 4; i++)
                su[(co_base + j) * 33 + px_base + i] = acc[j][i] + bj;
        }
        // issue W_proj load (overlaps squash; region free after GEMM1 sync)
        {
            uint32_t dstb = smem_u32(swp);
            const float* src = Wp_all + (size_t)e * 16384;
            for (int i = tid; i < 16384; i += 128) {
                int co = i >> 7, ci = i & 127;
                cp4(dstb + (uint32_t)(co * 129 + ci) * 4, src + i);
            }
            asm volatile("cp.async.commit_group;");
        }
        __syncthreads();

        // squash: sn per pixel, scale = sn/(1+sn)/(sqrt(sn)+eps)
        {
            int px = tid & 31, part = tid >> 5;
            float s = 0.f;
#pragma unroll 8
            for (int ci = part * 32; ci < part * 32 + 32; ++ci) {
                float v = su[ci * 33 + px];
                s = fmaf(v, v, s);
            }
            spart[part * 32 + px] = s;
        }
        __syncthreads();
        if (tid < 32) {
            float sn = spart[tid] + spart[32 + tid] + spart[64 + tid] + spart[96 + tid];
            ssc[tid] = sn / (1.f + sn) / (sqrtf(sn) + 1e-8f);
        }
        __syncthreads();
        for (int i = tid; i < 4096; i += 128) {
            int ci = i >> 5, px = i & 31;
            su[ci * 33 + px] *= ssc[px];
        }
        asm volatile("cp.async.wait_group 0;");
        __syncthreads();

        // ---- GEMM2: v = W_proj @ u, K=128 ----
#pragma unroll
        for (int j = 0; j < 8; j++)
#pragma unroll
            for (int i = 0; i < 4; i++) acc[j][i] = 0.f;
        {
            const float* wpb = swp + co_base * 129;
            const float* sub = su + px_base;
#pragma unroll 4
            for (int ci = 0; ci < 128; ++ci) {
                float a[8], bv[4];
#pragma unroll
                for (int j = 0; j < 8; j++) a[j] = wpb[j * 129 + ci];
#pragma unroll
                for (int i = 0; i < 4; i++) bv[i] = sub[ci * 33 + i];
#pragma unroll
                for (int j = 0; j < 8; j++)
#pragma unroll
                    for (int i = 0; i < 4; i++)
                        acc[j][i] = fmaf(a[j], bv[i], acc[j][i]);
            }
        }
        // bias + accumulate weighted output per gate
#pragma unroll
        for (int j = 0; j < 8; j++) {
            float bj = __ldg(&bp_all[e * CC + co_base + j]);
#pragma unroll
            for (int i = 0; i < 4; i++) acc[j][i] += bj;
        }
#pragma unroll
        for (int g = 0; g < NG; ++g) {
            float w = (g == 0) ? wg0 : (g == 1) ? wg1 : (g == 2) ? wg2 : wg3;
            if (w != 0.f) {
                float* yb = sy + g * 4224 + co_base * 33 + px_base;
#pragma unroll
                for (int j = 0; j < 8; j++)
#pragma unroll
                    for (int i = 0; i < 4; i++)
                        yb[j * 33 + i] += w * acc[j][i];
            }
        }
        __syncthreads();  // su/swp reused next expert
    }

    // write outputs (coalesced 32-float runs, 128B-aligned)
    {
        size_t base = (size_t)b * IMG + (size_t)row * 64 + seg * 32;
        for (int g = 0; g < NG; ++g) {
            const float* yg = sy + g * 4224;
            float* og = out + (size_t)g * YSZ + base;
            for (int i = tid; i < 4096; i += 128) {
                int co = i >> 5, px = i & 31;
                og[(size_t)co * HWPIX + px] = yg[co * 33 + px];
            }
        }
    }
}

// ---------------------------------------------------------------------------
extern "C" void kernel_launch(void* const* d_in, const int* in_sizes, int n_in,
                              void* d_out, int out_size) {
    const float* x  = (const float*)d_in[0];
    const float* g1 = (const float*)d_in[1];
    const float* g2 = (const float*)d_in[2];
    const float* g3 = (const float*)d_in[3];
    const float* g4 = (const float*)d_in[4];
    const float* Wc = (const float*)d_in[5];
    const float* bc = (const float*)d_in[6];
    const float* Wp = (const float*)d_in[7];
    const float* bp = (const float*)d_in[8];
    float* out = (float*)d_out;

    cudaFuncSetAttribute(moe_main, cudaFuncAttributeMaxDynamicSharedMemorySize, SMEM_BYTES);

    mean_kernel<<<BB * CC, 256>>>(x);
    gate_kernel<<<1, 32>>>(g1, g2, g3, g4, out + (out_size - 1));
    moe_main<<<BB * 128, 128, SMEM_BYTES>>>(x, Wc, bc, Wp, bp, out);
}